// round 17
// baseline (speedup 1.0000x reference)
#include <cuda_runtime.h>
#include <cuda_bf16.h>
#include <cstdint>
#include <math.h>

// CrossFrameAttention via mma.sync (tcgen05 feature-gated off under compute_103).
//   QK: bf16 hi/lo 3-term split; fragments via ldmatrix, manually double-buffered
//   softmax: per-warp online max in log2 domain (Q pre-scaled by log2e);
//            P = ex2.approx.f16x2 (packed); l accumulated by ones-MMA;
//            frames merged via log-sum-exp in reduce (split-k over frames)
//   AV: fp16 P x fp16 V single term
//   K/V tiles: cp.async.bulk + mbarrier double buffering
//   R17: prepass split 2x for occupancy; epilogue On staged via smem (coalesced)

#define SAI 9
#define NB 4
#define CKD 64
#define HWN 1024
#define NGRP 16
#define NQT 8

#define ROWB 144            // row pitch bytes (72 elems x 2B)
#define SPLITB 9216         // one split [64][72] bf16
#define KTILEB 18432        // K tile: [2 split][64][72]
#define VTILEB 9216         // V tile: [64ch][72key] fp16
#define QTILEB 18432        // one Q split: [128 q][72 ch] bf16
#define CHUNKB (KTILEB + VTILEB)

__device__ __align__(16) char g_KT[SAI * NB * NGRP * KTILEB];  // 10.6 MB
__device__ __align__(16) char g_VT[SAI * NB * NGRP * VTILEB];  // 5.3 MB
__device__ float g_On[SAI * NB * NQT * 64 * 128];              // 9.4 MB
__device__ float g_L [SAI * NB * NQT * 128];
__device__ float g_M [SAI * NB * NQT * 128];

// ---------------- helpers ----------------
__device__ __forceinline__ uint32_t smem_u32(const void* p) {
    uint32_t a;
    asm("{ .reg .u64 t; cvta.to.shared.u64 t, %1; cvt.u32.u64 %0, t; }" : "=r"(a) : "l"(p));
    return a;
}

__device__ __forceinline__ uint32_t cvt2bf(float hi, float lo) {
    uint32_t r;
    asm("cvt.rn.bf16x2.f32 %0, %1, %2;" : "=r"(r) : "f"(hi), "f"(lo));
    return r;
}

__device__ __forceinline__ uint32_t cvt2h(float hi, float lo) {
    uint32_t r;
    asm("cvt.rn.f16x2.f32 %0, %1, %2;" : "=r"(r) : "f"(hi), "f"(lo));
    return r;
}

__device__ __forceinline__ uint32_t hex2(uint32_t x) {
    uint32_t r;
    asm("ex2.approx.f16x2 %0, %1;" : "=r"(r) : "r"(x));
    return r;
}

__device__ __forceinline__ void ldsm4(uint32_t* r, uint32_t addr) {
    asm volatile("ldmatrix.sync.aligned.m8n8.x4.shared.b16 {%0,%1,%2,%3}, [%4];"
                 : "=r"(r[0]), "=r"(r[1]), "=r"(r[2]), "=r"(r[3]) : "r"(addr));
}

__device__ __forceinline__ void mma_bf16(float* c, const uint32_t* a,
                                         uint32_t b0, uint32_t b1) {
    asm volatile(
        "mma.sync.aligned.m16n8k16.row.col.f32.bf16.bf16.f32 "
        "{%0,%1,%2,%3}, {%4,%5,%6,%7}, {%8,%9}, {%0,%1,%2,%3};"
        : "+f"(c[0]), "+f"(c[1]), "+f"(c[2]), "+f"(c[3])
        : "r"(a[0]), "r"(a[1]), "r"(a[2]), "r"(a[3]), "r"(b0), "r"(b1));
}

__device__ __forceinline__ void mma_f16(float* c, const uint32_t* a,
                                        uint32_t b0, uint32_t b1) {
    asm volatile(
        "mma.sync.aligned.m16n8k16.row.col.f32.f16.f16.f32 "
        "{%0,%1,%2,%3}, {%4,%5,%6,%7}, {%8,%9}, {%0,%1,%2,%3};"
        : "+f"(c[0]), "+f"(c[1]), "+f"(c[2]), "+f"(c[3])
        : "r"(a[0]), "r"(a[1]), "r"(a[2]), "r"(a[3]), "r"(b0), "r"(b1));
}

// bulk async copy gmem -> smem with mbarrier complete_tx
__device__ __forceinline__ void bulk_ld(uint32_t dst, const void* src,
                                        uint32_t bytes, uint32_t mbar) {
    asm volatile(
        "cp.async.bulk.shared::cta.global.mbarrier::complete_tx::bytes "
        "[%0], [%1], %2, [%3];"
        :: "r"(dst), "l"(src), "r"(bytes), "r"(mbar) : "memory");
}

#define MBAR_INIT(m, c) \
    asm volatile("mbarrier.init.shared.b64 [%0], %1;" :: "r"(m), "r"(c) : "memory")
#define MBAR_EXPECT_TX(m, bytes) \
    asm volatile("mbarrier.arrive.expect_tx.shared.b64 _, [%0], %1;" \
                 :: "r"(m), "r"(bytes) : "memory")
#define FENCE_PROXY() asm volatile("fence.proxy.async.shared::cta;" ::: "memory")

__device__ __forceinline__ void mbar_wait(uint32_t mbar, uint32_t parity) {
    asm volatile(
        "{\n\t.reg .pred P1;\n\t"
        "WL_%=:\n\t"
        "mbarrier.try_wait.parity.acquire.cta.shared::cta.b64 P1, [%0], %1;\n\t"
        "@P1 bra.uni WD_%=;\n\t"
        "bra.uni WL_%=;\n\t"
        "WD_%=:\n\t}"
        :: "r"(mbar), "r"(parity) : "memory");
}

// ---------------- prepass ----------------
// 2 blocks per (sb, 64-key group); block handles 32 channels (h = bx&1).
__global__ __launch_bounds__(256)
void prepass(const float* __restrict__ gK, const float* __restrict__ gV)
{
    __shared__ __align__(16) __nv_bfloat16 T[2][64][32];   // K staging (8 KB)

    const int bx = blockIdx.x;
    const int h   = bx & 1;
    const int grp = (bx >> 1) & 15;
    const int sb  = bx >> 5;
    const int hwb = grp * 64;
    const int tid = threadIdx.x;
    const int tilebase = sb * 16 + grp;

    const float* kb = gK + (size_t)sb * CKD * HWN + hwb;
    const float* vb = gV + (size_t)sb * CKD * HWN + hwb;

    // V direct: fp16 [ch][key], channels [32h, 32h+32)
    {
        char* dv = g_VT + (size_t)tilebase * VTILEB;
#pragma unroll
        for (int i = 0; i < 2; i++) {
            int idx = tid + i * 256;                  // 512 float4 ops
            int c = 32 * h + (idx >> 4), k4 = (idx & 15) * 4;
            float4 f = *(const float4*)(vb + (size_t)c * HWN + k4);
            uint2 hh = make_uint2(cvt2h(f.y, f.x), cvt2h(f.w, f.z));
            *(uint2*)(dv + (size_t)c * ROWB + k4 * 2) = hh;
        }
    }

    // K: transpose channels [32h,32h+32) to [key][ch] h/l via smem
#pragma unroll
    for (int i = 0; i < 8; i++) {
        int idx = tid + i * 256;                      // 2048 elems
        int c32 = idx >> 6, k = idx & 63;
        float f = kb[(size_t)(32 * h + c32) * HWN + k];
        __nv_bfloat16 hh = __float2bfloat16(f);
        T[0][k][c32] = hh;
        T[1][k][c32] = __float2bfloat16(f - __bfloat162float(hh));
    }
    __syncthreads();
    {
        char* dk = g_KT + (size_t)tilebase * KTILEB;
#pragma unroll
        for (int i = 0; i < 2; i++) {
            int idx = tid + i * 256;                  // 512 uint4
            int sp = idx >> 8, rem = idx & 255;
            int k = rem >> 2, u = rem & 3;
            uint4 v = reinterpret_cast<const uint4*>(&T[sp][k][0])[u];
            *reinterpret_cast<uint4*>(dk + sp * SPLITB + (size_t)k * ROWB
                                      + h * 64 + u * 16) = v;
        }
    }
}

// ---------------- main ----------------
// smem: [0,128) keep bitmask; [128,144) mbarriers full[2];
//       [256, +36864) Q [2 split][128][72] bf16 (reused as Osm [64][132] fp32 in epilogue);
//       [37120, +36864) K [2 slot][2 split][64][72];
//       [73984, +18432) V [2 slot][64][72] fp16
#define MBOFF 128
#define QOFF 256
#define KOFF 37120
#define VOFF 73984
#define SM_BYTES 92416
#define OSTR 132

__global__ __launch_bounds__(256, 2)
void cfa_main(const float* __restrict__ gQ, const float* __restrict__ gD,
              const int* __restrict__ gS)
{
    extern __shared__ char raw[];
    uint32_t* KeepS = (uint32_t*)raw;
    const uint32_t sb32 = smem_u32(raw);
    const uint32_t QSB = sb32 + QOFF;
    const uint32_t KSB = sb32 + KOFF;
    const uint32_t VSB = sb32 + VOFF;

    const int qt = blockIdx.x, b = blockIdx.y, s = blockIdx.z;
    const int sb = s * NB + b;
    const int tid = threadIdx.x;
    const int w = tid >> 5, lane = tid & 31;
    const int g = lane >> 2, t = lane & 3;
    const int hw0 = qt * 128;

    // prologue: init mbarriers, kick off chunk 0 -> slot 0 (single thread)
    if (tid == 0) {
        MBAR_INIT(sb32 + MBOFF, 1);
        MBAR_INIT(sb32 + MBOFF + 8, 1);
        FENCE_PROXY();
        MBAR_EXPECT_TX(sb32 + MBOFF, CHUNKB);
        bulk_ld(KSB, g_KT + (size_t)(sb * NGRP) * KTILEB, KTILEB, sb32 + MBOFF);
        bulk_ld(VSB, g_VT + (size_t)(sb * NGRP) * VTILEB, VTILEB, sb32 + MBOFF);
    }

    // keep bitmask
    {
        float ddx = (float)gS[(b * SAI + s) * 2 + 0] - 5.f;
        float ddy = (float)gS[(b * SAI + s) * 2 + 1] - 5.f;
        float dist = sqrtf(ddx * ddx + ddy * ddy);
#pragma unroll
        for (int r = 0; r < 4; r++) {
            unsigned bit = fabsf(dist * gD[b * HWN + r * 256 + tid]) > 0.5f ? 1u : 0u;
            unsigned word = __ballot_sync(0xffffffffu, bit);
            if (lane == 0) KeepS[r * 8 + w] = word;
        }
    }

    // Q tile: [q][c] bf16 h/l into smem, PRE-SCALED by log2(e)
    {
        const float* qp = gQ + (size_t)b * CKD * HWN + hw0;
        __nv_bfloat16* qh = (__nv_bfloat16*)(raw + QOFF);
        __nv_bfloat16* ql = (__nv_bfloat16*)(raw + QOFF + QTILEB);
#pragma unroll
        for (int i = 0; i < 32; i++) {
            int idx = tid + i * 256;                 // 8192 = 64c x 128q
            int c = idx >> 7, q = idx & 127;
            float f = qp[(size_t)c * HWN + q] * 1.4426950408889634f;
            __nv_bfloat16 h = __float2bfloat16(f);
            qh[q * 72 + c] = h;
            ql[q * 72 + c] = __float2bfloat16(f - __bfloat162float(h));
        }
    }

    // ldsm addressing
    const uint32_t lrow = (uint32_t)((lane & 7) + ((lane >> 4) << 3)) * ROWB
                        + (uint32_t)(((lane >> 3) & 1) << 4);
    const uint32_t arow = (uint32_t)((lane & 7) + (((lane >> 3) & 1) << 3)) * ROWB
                        + (uint32_t)((lane >> 4) << 4);
    const uint32_t qbase = QSB + (uint32_t)(16 * w) * ROWB + arow;

    float Oacc[8][4];
#pragma unroll
    for (int j = 0; j < 8; j++)
#pragma unroll
        for (int r = 0; r < 4; r++) Oacc[j][r] = 0.f;
    float Lacc[4] = {0.f, 0.f, 0.f, 0.f};   // ones-MMA accumulator: [0]=l(qa), [2]=l(qa+8)
    float m0 = -1e4f, m1 = -1e4f;            // log2-domain running max
    const uint32_t ONES2 = 0x3C003C00u;      // fp16x2 {1.0, 1.0}

    __syncthreads();   // mbars + Q tile + keep mask visible

    for (int gc = 0; gc < NGRP; gc++) {
        const int slot = gc & 1;
        const uint32_t mb = sb32 + MBOFF + slot * 8;

        mbar_wait(mb, (gc >> 1) & 1);    // chunk gc resident in slot
        __syncthreads();                 // all warps finished compute of gc-1

        // prefetch gc+1 into slot^1 (single thread, 2 bulk ops)
        if (tid == 0 && gc + 1 < NGRP) {
            const uint32_t mbn = sb32 + MBOFF + (slot ^ 1) * 8;
            MBAR_EXPECT_TX(mbn, CHUNKB);
            bulk_ld(KSB + (slot ^ 1) * KTILEB,
                    g_KT + (size_t)(sb * NGRP + gc + 1) * KTILEB, KTILEB, mbn);
            bulk_ld(VSB + (slot ^ 1) * VTILEB,
                    g_VT + (size_t)(sb * NGRP + gc + 1) * VTILEB, VTILEB, mbn);
        }

        const uint32_t kbase = KSB + slot * KTILEB;
        const uint32_t vbase = VSB + slot * VTILEB;

        // ---- S = Qh*Kh + Qh*Kl + Ql*Kh (K fragments double-buffered) ----
        float Sacc[8][4];
#pragma unroll
        for (int j = 0; j < 8; j++)
#pragma unroll
            for (int r = 0; r < 4; r++) Sacc[j][r] = 0.f;

#pragma unroll
        for (int kk = 0; kk < 4; kk++) {
            uint32_t qh[4], ql[4];
            ldsm4(qh, qbase + kk * 32);
            ldsm4(ql, qbase + kk * 32 + QTILEB);

            uint32_t kf[2][8];
            ldsm4(&kf[0][0], kbase + kk * 32 + lrow);
            ldsm4(&kf[0][4], kbase + kk * 32 + lrow + SPLITB);
#pragma unroll
            for (int np = 0; np < 4; np++) {
                const int nb = np & 1;
                if (np < 3) {
                    uint32_t ah = kbase + (np + 1) * (16 * ROWB) + kk * 32 + lrow;
                    ldsm4(&kf[nb ^ 1][0], ah);
                    ldsm4(&kf[nb ^ 1][4], ah + SPLITB);
                }
                const uint32_t* f = kf[nb];
                mma_bf16(Sacc[2 * np],     qh, f[0], f[1]);
                mma_bf16(Sacc[2 * np + 1], qh, f[2], f[3]);
                mma_bf16(Sacc[2 * np],     qh, f[4], f[5]);
                mma_bf16(Sacc[2 * np + 1], qh, f[6], f[7]);
                mma_bf16(Sacc[2 * np],     ql, f[0], f[1]);
                mma_bf16(Sacc[2 * np + 1], ql, f[2], f[3]);
            }
        }

        // ---- per-warp online max (unmasked; over-estimate is ratio-safe) ----
        float r0mx = -1e30f, r1mx = -1e30f;
#pragma unroll
        for (int j = 0; j < 8; j++) {
            r0mx = fmaxf(r0mx, fmaxf(Sacc[j][0], Sacc[j][1]));
            r1mx = fmaxf(r1mx, fmaxf(Sacc[j][2], Sacc[j][3]));
        }
        r0mx = fmaxf(r0mx, __shfl_xor_sync(0xffffffffu, r0mx, 1));
        r0mx = fmaxf(r0mx, __shfl_xor_sync(0xffffffffu, r0mx, 2));
        r1mx = fmaxf(r1mx, __shfl_xor_sync(0xffffffffu, r1mx, 1));
        r1mx = fmaxf(r1mx, __shfl_xor_sync(0xffffffffu, r1mx, 2));

        float m0n = fmaxf(m0, r0mx), m1n = fmaxf(m1, r1mx);
        float sc0 = exp2f(m0 - m0n), sc1 = exp2f(m1 - m1n);
        m0 = m0n; m1 = m1n;
#pragma unroll
        for (int j = 0; j < 8; j++) {
            Oacc[j][0] *= sc0; Oacc[j][1] *= sc0;
            Oacc[j][2] *= sc1; Oacc[j][3] *= sc1;
        }
        Lacc[0] *= sc0; Lacc[2] *= sc1;

        // ---- P = mask & ex2.f16x2(s - m) ; fp16 fragments ----
        const unsigned w0 = KeepS[2 * gc], w1 = KeepS[2 * gc + 1];
        uint32_t PhA[8], PhB[8];
#pragma unroll
        for (int j = 0; j < 8; j++) {
            unsigned sel = (j < 4) ? w0 : w1;
            int sh = ((8 * j) & 31) + 2 * t;
            uint32_t mw = (((sel >> sh) & 1) ? 0x0000FFFFu : 0u)
                        | (((sel >> (sh + 1)) & 1) ? 0xFFFF0000u : 0u);
            uint32_t eA = cvt2h(Sacc[j][1] - m0, Sacc[j][0] - m0);
            uint32_t eB = cvt2h(Sacc[j][3] - m1, Sacc[j][2] - m1);
            PhA[j] = hex2(eA) & mw;
            PhB[j] = hex2(eB) & mw;
        }

        // ---- l += P * ones (4 MMAs; all B columns identical -> c0/c2 = row sums) ----
#pragma unroll
        for (int kk = 0; kk < 4; kk++) {
            uint32_t a[4] = {PhA[2 * kk], PhB[2 * kk], PhA[2 * kk + 1], PhB[2 * kk + 1]};
            mma_f16(Lacc, a, ONES2, ONES2);
        }

        // ---- O += P * V (V fragments double-buffered) ----
        {
            uint32_t vf[2][4];
            ldsm4(vf[0], vbase + lrow);
#pragma unroll
            for (int it = 0; it < 16; it++) {
                const int kk = it >> 2, np = it & 3;
                const int nb = it & 1;
                if (it < 15) {
                    const int kk2 = (it + 1) >> 2, np2 = (it + 1) & 3;
                    ldsm4(vf[nb ^ 1], vbase + np2 * (16 * ROWB) + kk2 * 32 + lrow);
                }
                uint32_t a[4] = {PhA[2 * kk], PhB[2 * kk], PhA[2 * kk + 1], PhB[2 * kk + 1]};
                mma_f16(Oacc[2 * np],     a, vf[nb][0], vf[nb][1]);
                mma_f16(Oacc[2 * np + 1], a, vf[nb][2], vf[nb][3]);
            }
        }
    }

    // ---- epilogue: stage O through smem, coalesced float4 store ----
    const size_t lb = (size_t)(sb * NQT + qt) * 128;
    if (t == 0) {
        g_L[lb + 16 * w + g]     = Lacc[0];
        g_L[lb + 16 * w + 8 + g] = Lacc[2];
        g_M[lb + 16 * w + g]     = m0;
        g_M[lb + 16 * w + 8 + g] = m1;
    }

    __syncthreads();   // all warps done with Q smem; safe to overlay Osm
    float* Osm = (float*)(raw + QOFF);       // [64][OSTR]
    const int qa = 16 * w + g;
#pragma unroll
    for (int j = 0; j < 8; j++) {
        int c = 8 * j + 2 * t;
        Osm[c * OSTR + qa]           = Oacc[j][0];
        Osm[(c + 1) * OSTR + qa]     = Oacc[j][1];
        Osm[c * OSTR + qa + 8]       = Oacc[j][2];
        Osm[(c + 1) * OSTR + qa + 8] = Oacc[j][3];
    }
    __syncthreads();
    {
        float* on = g_On + (size_t)(sb * NQT + qt) * 8192;   // [c][128 q]
#pragma unroll
        for (int i = 0; i < 8; i++) {
            int idx = tid + i * 256;                 // 2048 float4
            int c = idx >> 5, u = idx & 31;
            float4 v = *reinterpret_cast<const float4*>(&Osm[c * OSTR + u * 4]);
            *reinterpret_cast<float4*>(&on[c * 128 + u * 4]) = v;
        }
    }
}

// ---------------- reduce: log-sum-exp merge over frames (log2 domain) ----------------
// grid = NB*NQT*4 (c split 4-way), 512 threads, 4 c's per thread
__global__ __launch_bounds__(512)
void reduce_k(float* __restrict__ gO)
{
    const int blk = blockIdx.x;              // ((b*8 + qt)*4 + cpart)
    const int cpart = blk & 3;
    const int qt = (blk >> 2) & 7;
    const int b = blk >> 5;
    const int q = threadIdx.x & 127, cq = threadIdx.x >> 7;

    float m[SAI], wgt[SAI];
    float M = -1e30f;
#pragma unroll
    for (int f = 0; f < SAI; f++) {
        m[f] = g_M[((size_t)(f * NB + b) * NQT + qt) * 128 + q];
        M = fmaxf(M, m[f]);
    }
    float den = 0.f;
#pragma unroll
    for (int f = 0; f < SAI; f++) {
        wgt[f] = exp2f(m[f] - M);
        den += g_L[((size_t)(f * NB + b) * NQT + qt) * 128 + q] * wgt[f];
    }
    float dinv = 1.f / den;

#pragma unroll
    for (int ci = 0; ci < 4; ci++) {
        int c = cpart * 16 + cq * 4 + ci;
        float acc = 0.f;
#pragma unroll
        for (int f = 0; f < SAI; f++)
            acc += g_On[(size_t)((f * NB + b) * NQT + qt) * 8192 + c * 128 + q] * wgt[f];
        gO[((size_t)b * 64 + c) * HWN + qt * 128 + q] = acc * dinv;
    }
}

extern "C" void kernel_launch(void* const* d_in, const int* in_sizes, int n_in,
                              void* d_out, int out_size)
{
    const float* gK = (const float*)d_in[0];  // memory_keys   (9,4,64,32,32)
    const float* gV = (const float*)d_in[1];  // memory_values (9,4,64,32,32)
    const float* gQ = (const float*)d_in[2];  // query_query   (4,64,32,32)
    const float* gD = (const float*)d_in[3];  // disparity     (4,1,32,32)
    const int*   gS = (const int*)d_in[4];    // sequence_index(4,9,2)
    float* gO = (float*)d_out;                // (4,64,32,32)

    cudaFuncSetAttribute(cfa_main, cudaFuncAttributeMaxDynamicSharedMemorySize, SM_BYTES);

    prepass<<<SAI * NB * NGRP * 2, 256>>>(gK, gV);
    dim3 gr(NQT, NB, SAI);
    cfa_main<<<gr, 256, SM_BYTES>>>(gQ, gD, gS);
    reduce_k<<<NB * NQT * 4, 512>>>(gO);
}